// round 1
// baseline (speedup 1.0000x reference)
#include <cuda_runtime.h>

// CubicalModel_ISM: out[j]    = dot(X[r1(j)], p), r1(j) = inds1[2j]*28 + inds1[2j+1], j in [0,100)
//                   out[100+j]= dot(Y[r2(j)], p), r2(j) = inds2[2j]*28 + inds2[2j+1]
// Only 200 of the 1568 possible rows are needed -> compute only those.

#define Q 32768
#define QV (Q / 4)          // 8192 float4
#define NTHREADS 1024
#define W_DIM 28

__global__ __launch_bounds__(NTHREADS, 2)
void gathered_dot_kernel(const float* __restrict__ X,
                         const float* __restrict__ Y,
                         const float* __restrict__ p,
                         const int*   __restrict__ inds1,
                         const int*   __restrict__ inds2,
                         float* __restrict__ out)
{
    const int j = blockIdx.x;            // 0..199
    const bool second = (j >= 100);
    const int jj = second ? (j - 100) : j;
    const int* __restrict__ inds = second ? inds2 : inds1;
    const float* __restrict__ M  = second ? Y : X;

    const int r = inds[2 * jj] * W_DIM + inds[2 * jj + 1];

    const float4* __restrict__ row = reinterpret_cast<const float4*>(M + (size_t)r * Q);
    const float4* __restrict__ pv  = reinterpret_cast<const float4*>(p);

    float sum = 0.0f;
    // 8192 float4 / 1024 threads = 8 iterations; fully unrolled for MLP
    #pragma unroll 8
    for (int i = threadIdx.x; i < QV; i += NTHREADS) {
        float4 a = row[i];
        float4 b = pv[i];
        sum += a.x * b.x + a.y * b.y + a.z * b.z + a.w * b.w;
    }

    // intra-warp reduce
    #pragma unroll
    for (int off = 16; off > 0; off >>= 1)
        sum += __shfl_xor_sync(0xFFFFFFFFu, sum, off);

    __shared__ float warp_sums[NTHREADS / 32];
    const int lane = threadIdx.x & 31;
    const int wid  = threadIdx.x >> 5;
    if (lane == 0) warp_sums[wid] = sum;
    __syncthreads();

    if (wid == 0) {
        float s = (lane < NTHREADS / 32) ? warp_sums[lane] : 0.0f;
        #pragma unroll
        for (int off = 16; off > 0; off >>= 1)
            s += __shfl_xor_sync(0xFFFFFFFFu, s, off);
        if (lane == 0) out[j] = s;
    }
}

extern "C" void kernel_launch(void* const* d_in, const int* in_sizes, int n_in,
                              void* d_out, int out_size)
{
    // metadata order: X (784*32768 f32), Y (784*32768 f32), p (32768 f32),
    //                 inds1 (200 i32), inds2 (200 i32)
    const float* X    = (const float*)d_in[0];
    const float* Y    = (const float*)d_in[1];
    const float* p    = (const float*)d_in[2];
    const int* inds1  = (const int*)d_in[3];
    const int* inds2  = (const int*)d_in[4];
    float* out        = (float*)d_out;

    gathered_dot_kernel<<<200, NTHREADS>>>(X, Y, p, inds1, inds2, out);
}